// round 14
// baseline (speedup 1.0000x reference)
#include <cuda_runtime.h>
#include <cuda_fp16.h>
#include <math.h>
#include <stdint.h>

#define SEQ     2048
#define DMODEL  2048
#define NHEAD   16
#define FFDIM   8192
#define NTOK    4096
#define LN_EPS  1e-5f

// ---------------- scratch ----------------
__device__ __half g_h   [(size_t)NTOK * DMODEL];
__device__ __half g_qkv [(size_t)NTOK * 3 * DMODEL];
__device__ __half g_av  [(size_t)NTOK * DMODEL];
__device__ float  g_x1  [(size_t)NTOK * DMODEL];
__device__ __half g_ffn [(size_t)NTOK * FFDIM];
__device__ __half g_wqkv[(size_t)3 * DMODEL * DMODEL];  // [N][K]
__device__ __half g_wout[(size_t)DMODEL * DMODEL];
__device__ __half g_w1  [(size_t)FFDIM * DMODEL];
__device__ __half g_w2  [(size_t)DMODEL * FFDIM];

// ---------------- helpers ----------------
__device__ __forceinline__ uint32_t s2u(const void* p){
  uint32_t a;
  asm("{ .reg .u64 t; cvta.to.shared.u64 t, %1; cvt.u32.u64 %0, t; }" : "=r"(a) : "l"(p));
  return a;
}
__device__ __forceinline__ void cpa16(uint32_t dst, const void* src){
  asm volatile("cp.async.cg.shared.global [%0], [%1], 16;" :: "r"(dst), "l"(src));
}
__device__ __forceinline__ void cp_commit(){ asm volatile("cp.async.commit_group;"); }
__device__ __forceinline__ void cp_wait0(){ asm volatile("cp.async.wait_group 0;" ::: "memory"); }
__device__ __forceinline__ void cp_wait1(){ asm volatile("cp.async.wait_group 1;" ::: "memory"); }
__device__ __forceinline__ void mma16(float* c, const uint32_t* a, const uint32_t* b){
  asm volatile("mma.sync.aligned.m16n8k16.row.col.f32.f16.f16.f32 "
    "{%0,%1,%2,%3}, {%4,%5,%6,%7}, {%8,%9}, {%0,%1,%2,%3};"
    : "+f"(c[0]), "+f"(c[1]), "+f"(c[2]), "+f"(c[3])
    : "r"(a[0]), "r"(a[1]), "r"(a[2]), "r"(a[3]), "r"(b[0]), "r"(b[1]));
}
__device__ __forceinline__ void ldmx4(uint32_t* r, uint32_t addr){
  asm volatile("ldmatrix.sync.aligned.m8n8.x4.shared.b16 {%0,%1,%2,%3}, [%4];"
    : "=r"(r[0]), "=r"(r[1]), "=r"(r[2]), "=r"(r[3]) : "r"(addr));
}
__device__ __forceinline__ void ldmx2t(uint32_t& r0, uint32_t& r1, uint32_t addr){
  asm volatile("ldmatrix.sync.aligned.m8n8.x2.trans.shared.b16 {%0,%1}, [%2];"
    : "=r"(r0), "=r"(r1) : "r"(addr));
}
__device__ __forceinline__ uint32_t packh2(float lo, float hi){
  __half2 h = __floats2half2_rn(lo, hi);
  return *(uint32_t*)&h;
}
__device__ __forceinline__ float gelu_exact(float t){
  return 0.5f * t * (1.0f + erff(t * 0.70710678118654752f));
}

// ---- fused weight transpose: all 4 matrices, W[K][N] fp32 -> Wt[N][K] fp16 ----
#define WT_TILES 49152
__global__ __launch_bounds__(256) void wtrans_all(
    const float* __restrict__ qkv_w, __half* __restrict__ o_qkv,
    const float* __restrict__ out_w, __half* __restrict__ o_out,
    const float* __restrict__ w1,    __half* __restrict__ o_w1,
    const float* __restrict__ w2,    __half* __restrict__ o_w2)
{
  __shared__ float s[32][33];
  int bid = blockIdx.x;
  const float* W; __half* Wt; int K, N, nx, tile;
  if (bid < 12288){ W = qkv_w; Wt = o_qkv; K = 2048; N = 6144; nx = 192; tile = bid; }
  else if (bid < 16384){ W = out_w; Wt = o_out; K = 2048; N = 2048; nx = 64; tile = bid - 12288; }
  else if (bid < 32768){ W = w1; Wt = o_w1; K = 2048; N = 8192; nx = 256; tile = bid - 16384; }
  else { W = w2; Wt = o_w2; K = 8192; N = 2048; nx = 64; tile = bid - 32768; }
  int n0 = (tile % nx) * 32, k0 = (tile / nx) * 32;
  int tid = threadIdx.x;
  #pragma unroll
  for (int i = 0; i < 4; i++){
    int idx = tid + i * 256;
    int r = idx >> 5, c = idx & 31;
    s[r][c] = W[(size_t)(k0 + r) * N + n0 + c];
  }
  __syncthreads();
  #pragma unroll
  for (int i = 0; i < 2; i++){
    int c = tid + i * 256;
    int n = c >> 4, k2 = (c & 15) * 2;
    __half2 h = __floats2half2_rn(s[k2][n], s[k2 + 1][n]);
    *(__half2*)&Wt[(size_t)(n0 + n) * K + k0 + k2] = h;
  }
}

// ---- LayerNorm fp32 in -> fp16 out ----
__global__ __launch_bounds__(256) void ln_kernel(
    const float* __restrict__ x, const float* __restrict__ gamma,
    const float* __restrict__ beta, __half* __restrict__ out)
{
  int row = blockIdx.x;
  int tid = threadIdx.x;
  const float4* xr = (const float4*)(x + (size_t)row * DMODEL);
  float4 v0 = xr[tid];
  float4 v1 = xr[tid + 256];
  float s  = v0.x + v0.y + v0.z + v0.w + v1.x + v1.y + v1.z + v1.w;
  float sq = v0.x*v0.x + v0.y*v0.y + v0.z*v0.z + v0.w*v0.w
           + v1.x*v1.x + v1.y*v1.y + v1.z*v1.z + v1.w*v1.w;
  #pragma unroll
  for (int m = 16; m > 0; m >>= 1){
    s  += __shfl_xor_sync(0xffffffffu, s,  m);
    sq += __shfl_xor_sync(0xffffffffu, sq, m);
  }
  __shared__ float red_s[8], red_q[8], bc[2];
  int warp = tid >> 5, lane = tid & 31;
  if (lane == 0){ red_s[warp] = s; red_q[warp] = sq; }
  __syncthreads();
  if (tid == 0){
    float ts = 0.f, tq = 0.f;
    #pragma unroll
    for (int i = 0; i < 8; i++){ ts += red_s[i]; tq += red_q[i]; }
    float mu  = ts * (1.0f / DMODEL);
    float var = tq * (1.0f / DMODEL) - mu * mu;
    bc[0] = mu; bc[1] = rsqrtf(var + LN_EPS);
  }
  __syncthreads();
  float mu = bc[0], rinv = bc[1];
  const float4* gv = (const float4*)gamma;
  const float4* bv = (const float4*)beta;
  float4 g0 = gv[tid], b0 = bv[tid];
  float4 g1 = gv[tid + 256], b1 = bv[tid + 256];
  __half2* ov = (__half2*)(out + (size_t)row * DMODEL);
  ov[2*tid]           = __floats2half2_rn((v0.x-mu)*rinv*g0.x+b0.x, (v0.y-mu)*rinv*g0.y+b0.y);
  ov[2*tid + 1]       = __floats2half2_rn((v0.z-mu)*rinv*g0.z+b0.z, (v0.w-mu)*rinv*g0.w+b0.w);
  ov[512 + 2*tid]     = __floats2half2_rn((v1.x-mu)*rinv*g1.x+b1.x, (v1.y-mu)*rinv*g1.y+b1.y);
  ov[512 + 2*tid + 1] = __floats2half2_rn((v1.z-mu)*rinv*g1.z+b1.z, (v1.w-mu)*rinv*g1.w+b1.w);
}

// ---------------------------------------------------------------------------
// fp16 GEMM wide (R11): tile 128x256, BK=64, 2-stage, 256 thr, warp 64x64.
// ---------------------------------------------------------------------------
#define HW_AF   (128 * 72)
#define HW_BF   (256 * 72)
#define HW_STF  (HW_AF + HW_BF)
#define HW_STB  (HW_STF * 2)
#define HW_SMEM (2 * HW_STB)

template<int EPI>
__global__ __launch_bounds__(256, 1) void hgemm_w(
    const __half* __restrict__ A, const __half* __restrict__ Bt,
    const float* __restrict__ bias, __half* __restrict__ C, int N, int K)
{
  extern __shared__ __half smh[];
  int tid = threadIdx.x, lane = tid & 31, warp = tid >> 5;
  int bx = blockIdx.x, by = blockIdx.y;
  int wm = (warp >> 2) * 64, wn = (warp & 3) * 64;
  int gid = lane >> 2, tig = lane & 3;

  int ld_r = tid >> 3;
  int ld_k = (tid & 7) * 8;
  const __half* Ag = A + (size_t)(by * 128 + ld_r) * K + ld_k;
  const __half* Bg = Bt + (size_t)(bx * 256 + ld_r) * K + ld_k;

  uint32_t smb = s2u(smh);
  uint32_t asd = smb + (ld_r * 72 + ld_k) * 2;
  uint32_t bsd = smb + (HW_AF + ld_r * 72 + ld_k) * 2;

  uint32_t a_lm[4], b_lm[4];
  #pragma unroll
  for (int mi = 0; mi < 4; mi++)
    a_lm[mi] = smb + (((wm + mi * 16 + (lane & 15)) * 72) + ((lane >> 4) * 8)) * 2;
  #pragma unroll
  for (int tp = 0; tp < 4; tp++)
    b_lm[tp] = smb + (HW_AF
             + (wn + 16 * tp + ((lane & 16) ? 8 : 0) + (lane & 7)) * 72
             + ((lane & 8) ? 8 : 0)) * 2;

  float c[4][8][4];
  #pragma unroll
  for (int mi = 0; mi < 4; mi++)
    #pragma unroll
    for (int ni = 0; ni < 8; ni++)
      #pragma unroll
      for (int q = 0; q < 4; q++) c[mi][ni][q] = 0.f;

  int nk = K >> 6;
  auto issue = [&](int kb, int st){
    uint32_t off = st ? (uint32_t)HW_STB : 0u;
    const __half* ag = Ag + (size_t)kb * 64;
    const __half* bg = Bg + (size_t)kb * 64;
    #pragma unroll
    for (int i = 0; i < 4; i++)
      cpa16(asd + off + i * 32 * 72 * 2, ag + (size_t)(32 * i) * K);
    #pragma unroll
    for (int i = 0; i < 8; i++)
      cpa16(bsd + off + i * 32 * 72 * 2, bg + (size_t)(32 * i) * K);
    cp_commit();
  };
  issue(0, 0);

  for (int kb = 0; kb < nk; kb++){
    int st = kb & 1;
    cp_wait0();
    __syncthreads();
    if (kb + 1 < nk) issue(kb + 1, st ^ 1);
    uint32_t soff = st ? (uint32_t)HW_STB : 0u;
    #pragma unroll
    for (int ks = 0; ks < 4; ks++){
      uint32_t koff = soff + ks * 32;
      uint32_t a[4][4], b[8][2];
      #pragma unroll
      for (int mi = 0; mi < 4; mi++)
        ldmx4(a[mi], a_lm[mi] + koff);
      #pragma unroll
      for (int tp = 0; tp < 4; tp++){
        uint32_t r[4];
        ldmx4(r, b_lm[tp] + koff);
        b[2*tp][0] = r[0]; b[2*tp][1] = r[1];
        b[2*tp+1][0] = r[2]; b[2*tp+1][1] = r[3];
      }
      #pragma unroll
      for (int mi = 0; mi < 4; mi++)
        #pragma unroll
        for (int t = 0; t < 8; t++)
          mma16(c[mi][t], a[mi], b[t]);
    }
    __syncthreads();
  }

  #pragma unroll
  for (int ni = 0; ni < 8; ni++){
    int col = bx * 256 + wn + ni * 8 + 2 * tig;
    float bb0 = bias[col], bb1 = bias[col + 1];
    #pragma unroll
    for (int mi = 0; mi < 4; mi++){
      int row0 = by * 128 + wm + mi * 16 + gid;
      float v00 = c[mi][ni][0] + bb0, v01 = c[mi][ni][1] + bb1;
      float v10 = c[mi][ni][2] + bb0, v11 = c[mi][ni][3] + bb1;
      if (EPI == 1){
        v00 = gelu_exact(v00); v01 = gelu_exact(v01);
        v10 = gelu_exact(v10); v11 = gelu_exact(v11);
      }
      *(__half2*)&C[(size_t)row0 * N + col]       = __floats2half2_rn(v00, v01);
      *(__half2*)&C[(size_t)(row0 + 8) * N + col] = __floats2half2_rn(v10, v11);
    }
  }
}

// ---------------------------------------------------------------------------
// fp16 GEMM narrow: tile 64x128, BK=64, 2-stage, occ2, 256 thr, warp 32x32.
// 1024 CTAs -> finer wave quantization. bias + residual -> fp32.
// ---------------------------------------------------------------------------
#define HN_AF   (64 * 72)            // A tile halves
#define HN_BF   (128 * 72)
#define HN_STF  (HN_AF + HN_BF)      // 13824 halves per stage
#define HN_STB  (HN_STF * 2)         // 27648 bytes
#define HN_SMEM (2 * HN_STB)         // 55296 bytes

__global__ __launch_bounds__(256, 2) void hgemm_n(
    const __half* __restrict__ A, const __half* __restrict__ Bt,
    const float* __restrict__ bias, const float* __restrict__ res,
    float* __restrict__ C, int N, int K)
{
  extern __shared__ __half smh[];
  int tid = threadIdx.x, lane = tid & 31, warp = tid >> 5;
  int bx = blockIdx.x, by = blockIdx.y;
  int wm = (warp >> 2) * 32, wn = (warp & 3) * 32;
  int gid = lane >> 2, tig = lane & 3;

  int ld_r = tid >> 3;                 // 0..31
  int ld_k = (tid & 7) * 8;
  const __half* Ag = A + (size_t)(by * 64 + ld_r) * K + ld_k;
  const __half* Bg = Bt + (size_t)(bx * 128 + ld_r) * K + ld_k;

  uint32_t smb = s2u(smh);
  uint32_t asd = smb + (ld_r * 72 + ld_k) * 2;
  uint32_t bsd = smb + (HN_AF + ld_r * 72 + ld_k) * 2;

  uint32_t a_lm[2], b_lm[2];
  #pragma unroll
  for (int mi = 0; mi < 2; mi++)
    a_lm[mi] = smb + (((wm + mi * 16 + (lane & 15)) * 72) + ((lane >> 4) * 8)) * 2;
  #pragma unroll
  for (int tp = 0; tp < 2; tp++)
    b_lm[tp] = smb + (HN_AF
             + (wn + 16 * tp + ((lane & 16) ? 8 : 0) + (lane & 7)) * 72
             + ((lane & 8) ? 8 : 0)) * 2;

  float c[2][4][4];
  #pragma unroll
  for (int mi = 0; mi < 2; mi++)
    #pragma unroll
    for (int ni = 0; ni < 4; ni++)
      #pragma unroll
      for (int q = 0; q < 4; q++) c[mi][ni][q] = 0.f;

  int nk = K >> 6;
  auto issue = [&](int kb, int st){
    uint32_t off = st ? (uint32_t)HN_STB : 0u;
    const __half* ag = Ag + (size_t)kb * 64;
    const __half* bg = Bg + (size_t)kb * 64;
    // A: 64 rows (2 passes of 32), B: 128 rows (4 passes of 32)
    cpa16(asd + off, ag);
    cpa16(asd + off + 32 * 72 * 2, ag + (size_t)32 * K);
    #pragma unroll
    for (int i = 0; i < 4; i++)
      cpa16(bsd + off + i * 32 * 72 * 2, bg + (size_t)(32 * i) * K);
    cp_commit();
  };
  issue(0, 0);

  for (int kb = 0; kb < nk; kb++){
    int st = kb & 1;
    cp_wait0();
    __syncthreads();
    if (kb + 1 < nk) issue(kb + 1, st ^ 1);
    uint32_t soff = st ? (uint32_t)HN_STB : 0u;
    #pragma unroll
    for (int ks = 0; ks < 4; ks++){
      uint32_t koff = soff + ks * 32;
      uint32_t a[2][4], b[4][2];
      #pragma unroll
      for (int mi = 0; mi < 2; mi++)
        ldmx4(a[mi], a_lm[mi] + koff);
      #pragma unroll
      for (int tp = 0; tp < 2; tp++){
        uint32_t r[4];
        ldmx4(r, b_lm[tp] + koff);
        b[2*tp][0] = r[0]; b[2*tp][1] = r[1];
        b[2*tp+1][0] = r[2]; b[2*tp+1][1] = r[3];
      }
      #pragma unroll
      for (int mi = 0; mi < 2; mi++)
        #pragma unroll
        for (int t = 0; t < 4; t++)
          mma16(c[mi][t], a[mi], b[t]);
    }
    __syncthreads();
  }

  #pragma unroll
  for (int ni = 0; ni < 4; ni++){
    int col = bx * 128 + wn + ni * 8 + 2 * tig;
    float bb0 = bias[col], bb1 = bias[col + 1];
    #pragma unroll
    for (int mi = 0; mi < 2; mi++){
      int row0 = by * 64 + wm + mi * 16 + gid;
      float2 r0 = *(const float2*)&res[(size_t)row0 * N + col];
      float2 r1 = *(const float2*)&res[(size_t)(row0 + 8) * N + col];
      float2 v0 = make_float2(c[mi][ni][0] + bb0 + r0.x, c[mi][ni][1] + bb1 + r0.y);
      float2 v1 = make_float2(c[mi][ni][2] + bb0 + r1.x, c[mi][ni][3] + bb1 + r1.y);
      *(float2*)&C[(size_t)row0 * N + col]       = v0;
      *(float2*)&C[(size_t)(row0 + 8) * N + col] = v1;
    }
  }
}

// ---------------------------------------------------------------------------
// fp16 mma flash attention (unchanged; K-tile 128).
// ---------------------------------------------------------------------------
#define AT_TF   (128 * 136)
#define AT_STF  (2 * AT_TF)
#define AT_SMEM (2 * AT_STF * 2)

__global__ __launch_bounds__(256, 1) void attn_h(
    const __half* __restrict__ qkv, __half* __restrict__ av)
{
  extern __shared__ __half smh[];
  uint32_t sbase = s2u(smh);

  int qt = blockIdx.x, bh = blockIdx.y;
  int b = bh >> 4, h = bh & 15;
  int q0 = qt * 128;
  int tid = threadIdx.x, warp = tid >> 5, lane = tid & 31;
  int gid = lane >> 2, tig = lane & 3;
  int wq = warp * 16;
  const float scl = 0.08838834764831845f;

  const __half* base = qkv + (size_t)(b * SEQ) * (3 * DMODEL) + h * 128;

  int r0 = q0 + wq + gid;
  const __half* Qp0 = base + (size_t)r0 * (3 * DMODEL);
  const __half* Qp1 = Qp0 + (size_t)8 * (3 * DMODEL);
  uint32_t qa[8][4];
  #pragma unroll
  for (int j = 0; j < 8; j++){
    qa[j][0] = *(const uint32_t*)(Qp0 + 16 * j + 2 * tig);
    qa[j][1] = *(const uint32_t*)(Qp1 + 16 * j + 2 * tig);
    qa[j][2] = *(const uint32_t*)(Qp0 + 16 * j + 2 * tig + 8);
    qa[j][3] = *(const uint32_t*)(Qp1 + 16 * j + 2 * tig + 8);
  }

  float O[16][4];
  #pragma unroll
  for (int u = 0; u < 16; u++)
    #pragma unroll
    for (int q = 0; q < 4; q++) O[u][q] = 0.f;
  float m0 = -1e30f, m1 = -1e30f, l0 = 0.f, l1 = 0.f;

  int ntiles = qt + 1;
  int pf_r = tid >> 4, pf_d = (tid & 15) * 8;

  auto prefetch = [&](int kt, int buf){
    uint32_t db = sbase + (uint32_t)buf * AT_STF * 2;
    const __half* kg = base + DMODEL + (size_t)(kt * 128 + pf_r) * (3 * DMODEL) + pf_d;
    #pragma unroll
    for (int it = 0; it < 8; it++){
      uint32_t dk = db + ((pf_r + it * 16) * 136 + pf_d) * 2;
      const __half* src = kg + (size_t)(it * 16) * (3 * DMODEL);
      cpa16(dk, src);
      cpa16(dk + AT_TF * 2, src + DMODEL);
    }
    cp_commit();
  };
  prefetch(0, 0);

  for (int kt = 0; kt < ntiles; kt++){
    int buf = kt & 1;
    if (kt + 1 < ntiles){ prefetch(kt + 1, buf ^ 1); cp_wait1(); }
    else cp_wait0();
    __syncthreads();

    int k0 = kt * 128;
    {
      const __half* Ks = smh + buf * AT_STF;

      float s[16][4];
      #pragma unroll
      for (int t = 0; t < 16; t++)
        #pragma unroll
        for (int q = 0; q < 4; q++) s[t][q] = 0.f;
      #pragma unroll
      for (int j = 0; j < 8; j++){
        #pragma unroll
        for (int t = 0; t < 16; t++){
          const __half* bb = Ks + (8 * t + gid) * 136 + 16 * j;
          uint32_t bf[2];
          bf[0] = *(const uint32_t*)(bb + 2 * tig);
          bf[1] = *(const uint32_t*)(bb + 2 * tig + 8);
          mma16(s[t], qa[j], bf);
        }
      }

      bool dg = (kt == qt);
      float mx0 = -1e30f, mx1 = -1e30f;
      #pragma unroll
      for (int t = 0; t < 16; t++){
        float c0 = s[t][0] * scl, c1 = s[t][1] * scl;
        float c2 = s[t][2] * scl, c3 = s[t][3] * scl;
        if (dg){
          int g0 = k0 + 8 * t + 2 * tig;
          if (g0     > r0)     c0 = -1e30f;
          if (g0 + 1 > r0)     c1 = -1e30f;
          if (g0     > r0 + 8) c2 = -1e30f;
          if (g0 + 1 > r0 + 8) c3 = -1e30f;
        }
        s[t][0] = c0; s[t][1] = c1; s[t][2] = c2; s[t][3] = c3;
        mx0 = fmaxf(mx0, fmaxf(c0, c1));
        mx1 = fmaxf(mx1, fmaxf(c2, c3));
      }
      #pragma unroll
      for (int m = 1; m < 4; m <<= 1){
        mx0 = fmaxf(mx0, __shfl_xor_sync(0xffffffffu, mx0, m));
        mx1 = fmaxf(mx1, __shfl_xor_sync(0xffffffffu, mx1, m));
      }
      float mn0 = fmaxf(m0, mx0), mn1 = fmaxf(m1, mx1);
      float cr0 = __expf(m0 - mn0), cr1 = __expf(m1 - mn1);
      m0 = mn0; m1 = mn1;
      float ls0 = 0.f, ls1 = 0.f;
      #pragma unroll
      for (int t = 0; t < 16; t++){
        s[t][0] = __expf(s[t][0] - mn0);
        s[t][1] = __expf(s[t][1] - mn0);
        s[t][2] = __expf(s[t][2] - mn1);
        s[t][3] = __expf(s[t][3] - mn1);
        ls0 += s[t][0] + s[t][1];
        ls1 += s[t][2] + s[t][3];
      }
      #pragma unroll
      for (int m = 1; m < 4; m <<= 1){
        ls0 += __shfl_xor_sync(0xffffffffu, ls0, m);
        ls1 += __shfl_xor_sync(0xffffffffu, ls1, m);
      }
      l0 = l0 * cr0 + ls0;
      l1 = l1 * cr1 + ls1;
      #pragma unroll
      for (int u = 0; u < 16; u++){
        O[u][0] *= cr0; O[u][1] *= cr0;
        O[u][2] *= cr1; O[u][3] *= cr1;
      }

      #pragma unroll
      for (int j2 = 0; j2 < 8; j2++){
        uint32_t pa[4];
        pa[0] = packh2(s[2*j2][0],   s[2*j2][1]);
        pa[1] = packh2(s[2*j2][2],   s[2*j2][3]);
        pa[2] = packh2(s[2*j2+1][0], s[2*j2+1][1]);
        pa[3] = packh2(s[2*j2+1][2], s[2*j2+1][3]);
        uint32_t vrow = sbase + (uint32_t)buf * AT_STF * 2 + AT_TF * 2
                      + ((16 * j2 + (lane & 15)) * 136) * 2;
        #pragma unroll
        for (int u = 0; u < 16; u++){
          uint32_t b0, b1;
          ldmx2t(b0, b1, vrow + 16 * u);
          uint32_t bf[2] = {b0, b1};
          mma16(O[u], pa, bf);
        }
      }
    }
    __syncthreads();
  }

  float i0 = 1.0f / l0, i1 = 1.0f / l1;
  __half* o0 = av + ((size_t)(b * SEQ) + r0) * DMODEL + h * 128;
  __half* o1 = o0 + (size_t)8 * DMODEL;
  #pragma unroll
  for (int u = 0; u < 16; u++){
    *(__half2*)&o0[8 * u + 2 * tig] = __floats2half2_rn(O[u][0] * i0, O[u][1] * i0);
    *(__half2*)&o1[8 * u + 2 * tig] = __floats2half2_rn(O[u][2] * i1, O[u][3] * i1);
  }
}

// ---------------- launch ----------------
extern "C" void kernel_launch(void* const* d_in, const int* in_sizes, int n_in,
                              void* d_out, int out_size)
{
  const float* x     = (const float*)d_in[0];
  const float* ln1_g = (const float*)d_in[1];
  const float* ln1_b = (const float*)d_in[2];
  const float* qkv_w = (const float*)d_in[3];
  const float* qkv_b = (const float*)d_in[4];
  const float* out_w = (const float*)d_in[5];
  const float* out_b = (const float*)d_in[6];
  const float* ln2_g = (const float*)d_in[7];
  const float* ln2_b = (const float*)d_in[8];
  const float* w1    = (const float*)d_in[9];
  const float* b1    = (const float*)d_in[10];
  const float* w2    = (const float*)d_in[11];
  const float* b2    = (const float*)d_in[12];
  float* out = (float*)d_out;

  __half *h_p, *qkv_p, *av_p, *ffn_p, *wqkv_p, *wout_p, *w1_p, *w2_p;
  float *x1_p;
  cudaGetSymbolAddress((void**)&h_p,    g_h);
  cudaGetSymbolAddress((void**)&qkv_p,  g_qkv);
  cudaGetSymbolAddress((void**)&av_p,   g_av);
  cudaGetSymbolAddress((void**)&x1_p,   g_x1);
  cudaGetSymbolAddress((void**)&ffn_p,  g_ffn);
  cudaGetSymbolAddress((void**)&wqkv_p, g_wqkv);
  cudaGetSymbolAddress((void**)&wout_p, g_wout);
  cudaGetSymbolAddress((void**)&w1_p,   g_w1);
  cudaGetSymbolAddress((void**)&w2_p,   g_w2);

  cudaFuncSetAttribute(attn_h, cudaFuncAttributeMaxDynamicSharedMemorySize, AT_SMEM);
  cudaFuncSetAttribute(hgemm_w<0>, cudaFuncAttributeMaxDynamicSharedMemorySize, HW_SMEM);
  cudaFuncSetAttribute(hgemm_w<1>, cudaFuncAttributeMaxDynamicSharedMemorySize, HW_SMEM);
  cudaFuncSetAttribute(hgemm_n, cudaFuncAttributeMaxDynamicSharedMemorySize, HN_SMEM);

  wtrans_all<<<WT_TILES, 256>>>(qkv_w, wqkv_p, out_w, wout_p, w1, w1_p, w2, w2_p);

  ln_kernel<<<NTOK, 256>>>(x, ln1_g, ln1_b, h_p);

  hgemm_w<0><<<dim3(24, 32), 256, HW_SMEM>>>(h_p, wqkv_p, qkv_b, qkv_p,
                                             3 * DMODEL, DMODEL);

  attn_h<<<dim3(SEQ / 128, 2 * NHEAD), 256, AT_SMEM>>>(qkv_p, av_p);

  hgemm_n<<<dim3(16, 64), 256, HN_SMEM>>>(av_p, wout_p, out_b, x, x1_p,
                                          DMODEL, DMODEL);

  ln_kernel<<<NTOK, 256>>>(x1_p, ln2_g, ln2_b, h_p);

  hgemm_w<1><<<dim3(32, 32), 256, HW_SMEM>>>(h_p, w1_p, b1, ffn_p, FFDIM, DMODEL);

  hgemm_n<<<dim3(16, 64), 256, HN_SMEM>>>(ffn_p, w2_p, b2, x1_p, out,
                                          DMODEL, FFDIM);
}

// round 15
// speedup vs baseline: 1.5959x; 1.5959x over previous
#include <cuda_runtime.h>
#include <cuda_fp16.h>
#include <math.h>
#include <stdint.h>

#define SEQ     2048
#define DMODEL  2048
#define NHEAD   16
#define FFDIM   8192
#define NTOK    4096
#define LN_EPS  1e-5f

// ---------------- scratch ----------------
__device__ __half g_h   [(size_t)NTOK * DMODEL];
__device__ __half g_qkv [(size_t)NTOK * 3 * DMODEL];
__device__ __half g_av  [(size_t)NTOK * DMODEL];
__device__ float  g_x1  [(size_t)NTOK * DMODEL];
__device__ __half g_ffn [(size_t)NTOK * FFDIM];
__device__ __half g_wqkv[(size_t)3 * DMODEL * DMODEL];  // [N][K]
__device__ __half g_wout[(size_t)DMODEL * DMODEL];
__device__ __half g_w1  [(size_t)FFDIM * DMODEL];
__device__ __half g_w2  [(size_t)DMODEL * FFDIM];

// ---------------- helpers ----------------
__device__ __forceinline__ uint32_t s2u(const void* p){
  uint32_t a;
  asm("{ .reg .u64 t; cvta.to.shared.u64 t, %1; cvt.u32.u64 %0, t; }" : "=r"(a) : "l"(p));
  return a;
}
__device__ __forceinline__ void cpa16(uint32_t dst, const void* src){
  asm volatile("cp.async.cg.shared.global [%0], [%1], 16;" :: "r"(dst), "l"(src));
}
__device__ __forceinline__ void cp_commit(){ asm volatile("cp.async.commit_group;"); }
__device__ __forceinline__ void cp_wait0(){ asm volatile("cp.async.wait_group 0;" ::: "memory"); }
__device__ __forceinline__ void cp_wait1(){ asm volatile("cp.async.wait_group 1;" ::: "memory"); }
__device__ __forceinline__ void mma16(float* c, const uint32_t* a, const uint32_t* b){
  asm volatile("mma.sync.aligned.m16n8k16.row.col.f32.f16.f16.f32 "
    "{%0,%1,%2,%3}, {%4,%5,%6,%7}, {%8,%9}, {%0,%1,%2,%3};"
    : "+f"(c[0]), "+f"(c[1]), "+f"(c[2]), "+f"(c[3])
    : "r"(a[0]), "r"(a[1]), "r"(a[2]), "r"(a[3]), "r"(b[0]), "r"(b[1]));
}
__device__ __forceinline__ void ldmx4(uint32_t* r, uint32_t addr){
  asm volatile("ldmatrix.sync.aligned.m8n8.x4.shared.b16 {%0,%1,%2,%3}, [%4];"
    : "=r"(r[0]), "=r"(r[1]), "=r"(r[2]), "=r"(r[3]) : "r"(addr));
}
__device__ __forceinline__ void ldmx2t(uint32_t& r0, uint32_t& r1, uint32_t addr){
  asm volatile("ldmatrix.sync.aligned.m8n8.x2.trans.shared.b16 {%0,%1}, [%2];"
    : "=r"(r0), "=r"(r1) : "r"(addr));
}
__device__ __forceinline__ uint32_t packh2(float lo, float hi){
  __half2 h = __floats2half2_rn(lo, hi);
  return *(uint32_t*)&h;
}
__device__ __forceinline__ float gelu_exact(float t){
  return 0.5f * t * (1.0f + erff(t * 0.70710678118654752f));
}

// ---- fused weight transpose: all 4 matrices, W[K][N] fp32 -> Wt[N][K] fp16 ----
#define WT_TILES 49152
__global__ __launch_bounds__(256) void wtrans_all(
    const float* __restrict__ qkv_w, __half* __restrict__ o_qkv,
    const float* __restrict__ out_w, __half* __restrict__ o_out,
    const float* __restrict__ w1,    __half* __restrict__ o_w1,
    const float* __restrict__ w2,    __half* __restrict__ o_w2)
{
  __shared__ float s[32][33];
  int bid = blockIdx.x;
  const float* W; __half* Wt; int K, N, nx, tile;
  if (bid < 12288){ W = qkv_w; Wt = o_qkv; K = 2048; N = 6144; nx = 192; tile = bid; }
  else if (bid < 16384){ W = out_w; Wt = o_out; K = 2048; N = 2048; nx = 64; tile = bid - 12288; }
  else if (bid < 32768){ W = w1; Wt = o_w1; K = 2048; N = 8192; nx = 256; tile = bid - 16384; }
  else { W = w2; Wt = o_w2; K = 8192; N = 2048; nx = 64; tile = bid - 32768; }
  int n0 = (tile % nx) * 32, k0 = (tile / nx) * 32;
  int tid = threadIdx.x;
  #pragma unroll
  for (int i = 0; i < 4; i++){
    int idx = tid + i * 256;
    int r = idx >> 5, c = idx & 31;
    s[r][c] = W[(size_t)(k0 + r) * N + n0 + c];
  }
  __syncthreads();
  #pragma unroll
  for (int i = 0; i < 2; i++){
    int c = tid + i * 256;
    int n = c >> 4, k2 = (c & 15) * 2;
    __half2 h = __floats2half2_rn(s[k2][n], s[k2 + 1][n]);
    *(__half2*)&Wt[(size_t)(n0 + n) * K + k0 + k2] = h;
  }
}

// ---- LayerNorm fp32 in -> fp16 out ----
__global__ __launch_bounds__(256) void ln_kernel(
    const float* __restrict__ x, const float* __restrict__ gamma,
    const float* __restrict__ beta, __half* __restrict__ out)
{
  int row = blockIdx.x;
  int tid = threadIdx.x;
  const float4* xr = (const float4*)(x + (size_t)row * DMODEL);
  float4 v0 = xr[tid];
  float4 v1 = xr[tid + 256];
  float s  = v0.x + v0.y + v0.z + v0.w + v1.x + v1.y + v1.z + v1.w;
  float sq = v0.x*v0.x + v0.y*v0.y + v0.z*v0.z + v0.w*v0.w
           + v1.x*v1.x + v1.y*v1.y + v1.z*v1.z + v1.w*v1.w;
  #pragma unroll
  for (int m = 16; m > 0; m >>= 1){
    s  += __shfl_xor_sync(0xffffffffu, s,  m);
    sq += __shfl_xor_sync(0xffffffffu, sq, m);
  }
  __shared__ float red_s[8], red_q[8], bc[2];
  int warp = tid >> 5, lane = tid & 31;
  if (lane == 0){ red_s[warp] = s; red_q[warp] = sq; }
  __syncthreads();
  if (tid == 0){
    float ts = 0.f, tq = 0.f;
    #pragma unroll
    for (int i = 0; i < 8; i++){ ts += red_s[i]; tq += red_q[i]; }
    float mu  = ts * (1.0f / DMODEL);
    float var = tq * (1.0f / DMODEL) - mu * mu;
    bc[0] = mu; bc[1] = rsqrtf(var + LN_EPS);
  }
  __syncthreads();
  float mu = bc[0], rinv = bc[1];
  const float4* gv = (const float4*)gamma;
  const float4* bv = (const float4*)beta;
  float4 g0 = gv[tid], b0 = bv[tid];
  float4 g1 = gv[tid + 256], b1 = bv[tid + 256];
  __half2* ov = (__half2*)(out + (size_t)row * DMODEL);
  ov[2*tid]           = __floats2half2_rn((v0.x-mu)*rinv*g0.x+b0.x, (v0.y-mu)*rinv*g0.y+b0.y);
  ov[2*tid + 1]       = __floats2half2_rn((v0.z-mu)*rinv*g0.z+b0.z, (v0.w-mu)*rinv*g0.w+b0.w);
  ov[512 + 2*tid]     = __floats2half2_rn((v1.x-mu)*rinv*g1.x+b1.x, (v1.y-mu)*rinv*g1.y+b1.y);
  ov[512 + 2*tid + 1] = __floats2half2_rn((v1.z-mu)*rinv*g1.z+b1.z, (v1.w-mu)*rinv*g1.w+b1.w);
}

// ---------------------------------------------------------------------------
// fp16 GEMM wide: tile 128x256, BK=64, 2-stage, 256 thr, warp 64x64, ldmatrix.
// ---------------------------------------------------------------------------
#define HW_AF   (128 * 72)
#define HW_BF   (256 * 72)
#define HW_STF  (HW_AF + HW_BF)
#define HW_STB  (HW_STF * 2)
#define HW_SMEM (2 * HW_STB)

template<int EPI>
__global__ __launch_bounds__(256, 1) void hgemm_w(
    const __half* __restrict__ A, const __half* __restrict__ Bt,
    const float* __restrict__ bias, __half* __restrict__ C, int N, int K)
{
  extern __shared__ __half smh[];
  int tid = threadIdx.x, lane = tid & 31, warp = tid >> 5;
  int bx = blockIdx.x, by = blockIdx.y;
  int wm = (warp >> 2) * 64, wn = (warp & 3) * 64;
  int gid = lane >> 2, tig = lane & 3;

  int ld_r = tid >> 3;
  int ld_k = (tid & 7) * 8;
  const __half* Ag = A + (size_t)(by * 128 + ld_r) * K + ld_k;
  const __half* Bg = Bt + (size_t)(bx * 256 + ld_r) * K + ld_k;

  uint32_t smb = s2u(smh);
  uint32_t asd = smb + (ld_r * 72 + ld_k) * 2;
  uint32_t bsd = smb + (HW_AF + ld_r * 72 + ld_k) * 2;

  uint32_t a_lm[4], b_lm[4];
  #pragma unroll
  for (int mi = 0; mi < 4; mi++)
    a_lm[mi] = smb + (((wm + mi * 16 + (lane & 15)) * 72) + ((lane >> 4) * 8)) * 2;
  #pragma unroll
  for (int tp = 0; tp < 4; tp++)
    b_lm[tp] = smb + (HW_AF
             + (wn + 16 * tp + ((lane & 16) ? 8 : 0) + (lane & 7)) * 72
             + ((lane & 8) ? 8 : 0)) * 2;

  float c[4][8][4];
  #pragma unroll
  for (int mi = 0; mi < 4; mi++)
    #pragma unroll
    for (int ni = 0; ni < 8; ni++)
      #pragma unroll
      for (int q = 0; q < 4; q++) c[mi][ni][q] = 0.f;

  int nk = K >> 6;
  auto issue = [&](int kb, int st){
    uint32_t off = st ? (uint32_t)HW_STB : 0u;
    const __half* ag = Ag + (size_t)kb * 64;
    const __half* bg = Bg + (size_t)kb * 64;
    #pragma unroll
    for (int i = 0; i < 4; i++)
      cpa16(asd + off + i * 32 * 72 * 2, ag + (size_t)(32 * i) * K);
    #pragma unroll
    for (int i = 0; i < 8; i++)
      cpa16(bsd + off + i * 32 * 72 * 2, bg + (size_t)(32 * i) * K);
    cp_commit();
  };
  issue(0, 0);

  for (int kb = 0; kb < nk; kb++){
    int st = kb & 1;
    cp_wait0();
    __syncthreads();
    if (kb + 1 < nk) issue(kb + 1, st ^ 1);
    uint32_t soff = st ? (uint32_t)HW_STB : 0u;
    #pragma unroll
    for (int ks = 0; ks < 4; ks++){
      uint32_t koff = soff + ks * 32;
      uint32_t a[4][4], b[8][2];
      #pragma unroll
      for (int mi = 0; mi < 4; mi++)
        ldmx4(a[mi], a_lm[mi] + koff);
      #pragma unroll
      for (int tp = 0; tp < 4; tp++){
        uint32_t r[4];
        ldmx4(r, b_lm[tp] + koff);
        b[2*tp][0] = r[0]; b[2*tp][1] = r[1];
        b[2*tp+1][0] = r[2]; b[2*tp+1][1] = r[3];
      }
      #pragma unroll
      for (int mi = 0; mi < 4; mi++)
        #pragma unroll
        for (int t = 0; t < 8; t++)
          mma16(c[mi][t], a[mi], b[t]);
    }
    __syncthreads();
  }

  #pragma unroll
  for (int ni = 0; ni < 8; ni++){
    int col = bx * 256 + wn + ni * 8 + 2 * tig;
    float bb0 = bias[col], bb1 = bias[col + 1];
    #pragma unroll
    for (int mi = 0; mi < 4; mi++){
      int row0 = by * 128 + wm + mi * 16 + gid;
      float v00 = c[mi][ni][0] + bb0, v01 = c[mi][ni][1] + bb1;
      float v10 = c[mi][ni][2] + bb0, v11 = c[mi][ni][3] + bb1;
      if (EPI == 1){
        v00 = gelu_exact(v00); v01 = gelu_exact(v01);
        v10 = gelu_exact(v10); v11 = gelu_exact(v11);
      }
      *(__half2*)&C[(size_t)row0 * N + col]       = __floats2half2_rn(v00, v01);
      *(__half2*)&C[(size_t)(row0 + 8) * N + col] = __floats2half2_rn(v10, v11);
    }
  }
}

// ---------------------------------------------------------------------------
// fp16 GEMM narrow: tile 128x128, BK=64, 2-stage, occ2, 256 thr, warp 64x32.
// bias + residual -> fp32.
// ---------------------------------------------------------------------------
#define HN_AF   (128 * 72)
#define HN_STF  (2 * HN_AF)
#define HN_STB  (HN_STF * 2)
#define HN_SMEM (2 * HN_STB)

__global__ __launch_bounds__(256, 2) void hgemm_n(
    const __half* __restrict__ A, const __half* __restrict__ Bt,
    const float* __restrict__ bias, const float* __restrict__ res,
    float* __restrict__ C, int N, int K)
{
  extern __shared__ __half smh[];
  int tid = threadIdx.x, lane = tid & 31, warp = tid >> 5;
  int bx = blockIdx.x, by = blockIdx.y;
  int wm = (warp >> 2) * 64, wn = (warp & 3) * 32;
  int gid = lane >> 2, tig = lane & 3;

  int ld_r = tid >> 3;
  int ld_k = (tid & 7) * 8;
  const __half* Ag = A + (size_t)(by * 128 + ld_r) * K + ld_k;
  const __half* Bg = Bt + (size_t)(bx * 128 + ld_r) * K + ld_k;

  uint32_t smb = s2u(smh);
  uint32_t asd = smb + (ld_r * 72 + ld_k) * 2;
  uint32_t bsd = smb + (HN_AF + ld_r * 72 + ld_k) * 2;

  uint32_t a_lm[4], b_lm[2];
  #pragma unroll
  for (int mi = 0; mi < 4; mi++)
    a_lm[mi] = smb + (((wm + mi * 16 + (lane & 15)) * 72) + ((lane >> 4) * 8)) * 2;
  #pragma unroll
  for (int tp = 0; tp < 2; tp++)
    b_lm[tp] = smb + (HN_AF
             + (wn + 16 * tp + ((lane & 16) ? 8 : 0) + (lane & 7)) * 72
             + ((lane & 8) ? 8 : 0)) * 2;

  float c[4][4][4];
  #pragma unroll
  for (int mi = 0; mi < 4; mi++)
    #pragma unroll
    for (int ni = 0; ni < 4; ni++)
      #pragma unroll
      for (int q = 0; q < 4; q++) c[mi][ni][q] = 0.f;

  int nk = K >> 6;
  auto issue = [&](int kb, int st){
    uint32_t off = st ? (uint32_t)HN_STB : 0u;
    const __half* ag = Ag + (size_t)kb * 64;
    const __half* bg = Bg + (size_t)kb * 64;
    #pragma unroll
    for (int i = 0; i < 4; i++){
      cpa16(asd + off + i * 32 * 72 * 2, ag + (size_t)(32 * i) * K);
      cpa16(bsd + off + i * 32 * 72 * 2, bg + (size_t)(32 * i) * K);
    }
    cp_commit();
  };
  issue(0, 0);

  for (int kb = 0; kb < nk; kb++){
    int st = kb & 1;
    cp_wait0();
    __syncthreads();
    if (kb + 1 < nk) issue(kb + 1, st ^ 1);
    uint32_t soff = st ? (uint32_t)HN_STB : 0u;
    #pragma unroll
    for (int ks = 0; ks < 4; ks++){
      uint32_t koff = soff + ks * 32;
      uint32_t a[4][4], b[4][2];
      #pragma unroll
      for (int mi = 0; mi < 4; mi++)
        ldmx4(a[mi], a_lm[mi] + koff);
      #pragma unroll
      for (int tp = 0; tp < 2; tp++){
        uint32_t r[4];
        ldmx4(r, b_lm[tp] + koff);
        b[2*tp][0] = r[0]; b[2*tp][1] = r[1];
        b[2*tp+1][0] = r[2]; b[2*tp+1][1] = r[3];
      }
      #pragma unroll
      for (int mi = 0; mi < 4; mi++)
        #pragma unroll
        for (int t = 0; t < 4; t++)
          mma16(c[mi][t], a[mi], b[t]);
    }
    __syncthreads();
  }

  #pragma unroll
  for (int ni = 0; ni < 4; ni++){
    int col = bx * 128 + wn + ni * 8 + 2 * tig;
    float bb0 = bias[col], bb1 = bias[col + 1];
    #pragma unroll
    for (int mi = 0; mi < 4; mi++){
      int row0 = by * 128 + wm + mi * 16 + gid;
      float2 r0 = *(const float2*)&res[(size_t)row0 * N + col];
      float2 r1 = *(const float2*)&res[(size_t)(row0 + 8) * N + col];
      float2 v0 = make_float2(c[mi][ni][0] + bb0 + r0.x, c[mi][ni][1] + bb1 + r0.y);
      float2 v1 = make_float2(c[mi][ni][2] + bb0 + r1.x, c[mi][ni][3] + bb1 + r1.y);
      *(float2*)&C[(size_t)row0 * N + col]       = v0;
      *(float2*)&C[(size_t)(row0 + 8) * N + col] = v1;
    }
  }
}

// ---------------------------------------------------------------------------
// fp16 mma flash attention (K-tile 128).
// ---------------------------------------------------------------------------
#define AT_TF   (128 * 136)
#define AT_STF  (2 * AT_TF)
#define AT_SMEM (2 * AT_STF * 2)

__global__ __launch_bounds__(256, 1) void attn_h(
    const __half* __restrict__ qkv, __half* __restrict__ av)
{
  extern __shared__ __half smh[];
  uint32_t sbase = s2u(smh);

  int qt = blockIdx.x, bh = blockIdx.y;
  int b = bh >> 4, h = bh & 15;
  int q0 = qt * 128;
  int tid = threadIdx.x, warp = tid >> 5, lane = tid & 31;
  int gid = lane >> 2, tig = lane & 3;
  int wq = warp * 16;
  const float scl = 0.08838834764831845f;

  const __half* base = qkv + (size_t)(b * SEQ) * (3 * DMODEL) + h * 128;

  int r0 = q0 + wq + gid;
  const __half* Qp0 = base + (size_t)r0 * (3 * DMODEL);
  const __half* Qp1 = Qp0 + (size_t)8 * (3 * DMODEL);
  uint32_t qa[8][4];
  #pragma unroll
  for (int j = 0; j < 8; j++){
    qa[j][0] = *(const uint32_t*)(Qp0 + 16 * j + 2 * tig);
    qa[j][1] = *(const uint32_t*)(Qp1 + 16 * j + 2 * tig);
    qa[j][2] = *(const uint32_t*)(Qp0 + 16 * j + 2 * tig + 8);
    qa[j][3] = *(const uint32_t*)(Qp1 + 16 * j + 2 * tig + 8);
  }

  float O[16][4];
  #pragma unroll
  for (int u = 0; u < 16; u++)
    #pragma unroll
    for (int q = 0; q < 4; q++) O[u][q] = 0.f;
  float m0 = -1e30f, m1 = -1e30f, l0 = 0.f, l1 = 0.f;

  int ntiles = qt + 1;
  int pf_r = tid >> 4, pf_d = (tid & 15) * 8;

  auto prefetch = [&](int kt, int buf){
    uint32_t db = sbase + (uint32_t)buf * AT_STF * 2;
    const __half* kg = base + DMODEL + (size_t)(kt * 128 + pf_r) * (3 * DMODEL) + pf_d;
    #pragma unroll
    for (int it = 0; it < 8; it++){
      uint32_t dk = db + ((pf_r + it * 16) * 136 + pf_d) * 2;
      const __half* src = kg + (size_t)(it * 16) * (3 * DMODEL);
      cpa16(dk, src);
      cpa16(dk + AT_TF * 2, src + DMODEL);
    }
    cp_commit();
  };
  prefetch(0, 0);

  for (int kt = 0; kt < ntiles; kt++){
    int buf = kt & 1;
    if (kt + 1 < ntiles){ prefetch(kt + 1, buf ^ 1); cp_wait1(); }
    else cp_wait0();
    __syncthreads();

    int k0 = kt * 128;
    {
      const __half* Ks = smh + buf * AT_STF;

      float s[16][4];
      #pragma unroll
      for (int t = 0; t < 16; t++)
        #pragma unroll
        for (int q = 0; q < 4; q++) s[t][q] = 0.f;
      #pragma unroll
      for (int j = 0; j < 8; j++){
        #pragma unroll
        for (int t = 0; t < 16; t++){
          const __half* bb = Ks + (8 * t + gid) * 136 + 16 * j;
          uint32_t bf[2];
          bf[0] = *(const uint32_t*)(bb + 2 * tig);
          bf[1] = *(const uint32_t*)(bb + 2 * tig + 8);
          mma16(s[t], qa[j], bf);
        }
      }

      bool dg = (kt == qt);
      float mx0 = -1e30f, mx1 = -1e30f;
      #pragma unroll
      for (int t = 0; t < 16; t++){
        float c0 = s[t][0] * scl, c1 = s[t][1] * scl;
        float c2 = s[t][2] * scl, c3 = s[t][3] * scl;
        if (dg){
          int g0 = k0 + 8 * t + 2 * tig;
          if (g0     > r0)     c0 = -1e30f;
          if (g0 + 1 > r0)     c1 = -1e30f;
          if (g0     > r0 + 8) c2 = -1e30f;
          if (g0 + 1 > r0 + 8) c3 = -1e30f;
        }
        s[t][0] = c0; s[t][1] = c1; s[t][2] = c2; s[t][3] = c3;
        mx0 = fmaxf(mx0, fmaxf(c0, c1));
        mx1 = fmaxf(mx1, fmaxf(c2, c3));
      }
      #pragma unroll
      for (int m = 1; m < 4; m <<= 1){
        mx0 = fmaxf(mx0, __shfl_xor_sync(0xffffffffu, mx0, m));
        mx1 = fmaxf(mx1, __shfl_xor_sync(0xffffffffu, mx1, m));
      }
      float mn0 = fmaxf(m0, mx0), mn1 = fmaxf(m1, mx1);
      float cr0 = __expf(m0 - mn0), cr1 = __expf(m1 - mn1);
      m0 = mn0; m1 = mn1;
      float ls0 = 0.f, ls1 = 0.f;
      #pragma unroll
      for (int t = 0; t < 16; t++){
        s[t][0] = __expf(s[t][0] - mn0);
        s[t][1] = __expf(s[t][1] - mn0);
        s[t][2] = __expf(s[t][2] - mn1);
        s[t][3] = __expf(s[t][3] - mn1);
        ls0 += s[t][0] + s[t][1];
        ls1 += s[t][2] + s[t][3];
      }
      #pragma unroll
      for (int m = 1; m < 4; m <<= 1){
        ls0 += __shfl_xor_sync(0xffffffffu, ls0, m);
        ls1 += __shfl_xor_sync(0xffffffffu, ls1, m);
      }
      l0 = l0 * cr0 + ls0;
      l1 = l1 * cr1 + ls1;
      #pragma unroll
      for (int u = 0; u < 16; u++){
        O[u][0] *= cr0; O[u][1] *= cr0;
        O[u][2] *= cr1; O[u][3] *= cr1;
      }

      #pragma unroll
      for (int j2 = 0; j2 < 8; j2++){
        uint32_t pa[4];
        pa[0] = packh2(s[2*j2][0],   s[2*j2][1]);
        pa[1] = packh2(s[2*j2][2],   s[2*j2][3]);
        pa[2] = packh2(s[2*j2+1][0], s[2*j2+1][1]);
        pa[3] = packh2(s[2*j2+1][2], s[2*j2+1][3]);
        uint32_t vrow = sbase + (uint32_t)buf * AT_STF * 2 + AT_TF * 2
                      + ((16 * j2 + (lane & 15)) * 136) * 2;
        #pragma unroll
        for (int u = 0; u < 16; u++){
          uint32_t b0, b1;
          ldmx2t(b0, b1, vrow + 16 * u);
          uint32_t bf[2] = {b0, b1};
          mma16(O[u], pa, bf);
        }
      }
    }
    __syncthreads();
  }

  float i0 = 1.0f / l0, i1 = 1.0f / l1;
  __half* o0 = av + ((size_t)(b * SEQ) + r0) * DMODEL + h * 128;
  __half* o1 = o0 + (size_t)8 * DMODEL;
  #pragma unroll
  for (int u = 0; u < 16; u++){
    *(__half2*)&o0[8 * u + 2 * tig] = __floats2half2_rn(O[u][0] * i0, O[u][1] * i0);
    *(__half2*)&o1[8 * u + 2 * tig] = __floats2half2_rn(O[u][2] * i1, O[u][3] * i1);
  }
}

// ---------------- launch ----------------
extern "C" void kernel_launch(void* const* d_in, const int* in_sizes, int n_in,
                              void* d_out, int out_size)
{
  const float* x     = (const float*)d_in[0];
  const float* ln1_g = (const float*)d_in[1];
  const float* ln1_b = (const float*)d_in[2];
  const float* qkv_w = (const float*)d_in[3];
  const float* qkv_b = (const float*)d_in[4];
  const float* out_w = (const float*)d_in[5];
  const float* out_b = (const float*)d_in[6];
  const float* ln2_g = (const float*)d_in[7];
  const float* ln2_b = (const float*)d_in[8];
  const float* w1    = (const float*)d_in[9];
  const float* b1    = (const float*)d_in[10];
  const float* w2    = (const float*)d_in[11];
  const float* b2    = (const float*)d_in[12];
  float* out = (float*)d_out;

  __half *h_p, *qkv_p, *av_p, *ffn_p, *wqkv_p, *wout_p, *w1_p, *w2_p;
  float *x1_p;
  cudaGetSymbolAddress((void**)&h_p,    g_h);
  cudaGetSymbolAddress((void**)&qkv_p,  g_qkv);
  cudaGetSymbolAddress((void**)&av_p,   g_av);
  cudaGetSymbolAddress((void**)&x1_p,   g_x1);
  cudaGetSymbolAddress((void**)&ffn_p,  g_ffn);
  cudaGetSymbolAddress((void**)&wqkv_p, g_wqkv);
  cudaGetSymbolAddress((void**)&wout_p, g_wout);
  cudaGetSymbolAddress((void**)&w1_p,   g_w1);
  cudaGetSymbolAddress((void**)&w2_p,   g_w2);

  cudaFuncSetAttribute(attn_h, cudaFuncAttributeMaxDynamicSharedMemorySize, AT_SMEM);
  cudaFuncSetAttribute(hgemm_w<0>, cudaFuncAttributeMaxDynamicSharedMemorySize, HW_SMEM);
  cudaFuncSetAttribute(hgemm_w<1>, cudaFuncAttributeMaxDynamicSharedMemorySize, HW_SMEM);
  cudaFuncSetAttribute(hgemm_n, cudaFuncAttributeMaxDynamicSharedMemorySize, HN_SMEM);

  wtrans_all<<<WT_TILES, 256>>>(qkv_w, wqkv_p, out_w, wout_p, w1, w1_p, w2, w2_p);

  ln_kernel<<<NTOK, 256>>>(x, ln1_g, ln1_b, h_p);

  hgemm_w<0><<<dim3(24, 32), 256, HW_SMEM>>>(h_p, wqkv_p, qkv_b, qkv_p,
                                             3 * DMODEL, DMODEL);

  attn_h<<<dim3(SEQ / 128, 2 * NHEAD), 256, AT_SMEM>>>(qkv_p, av_p);

  hgemm_n<<<dim3(16, 32), 256, HN_SMEM>>>(av_p, wout_p, out_b, x, x1_p,
                                          DMODEL, DMODEL);

  ln_kernel<<<NTOK, 256>>>(x1_p, ln2_g, ln2_b, h_p);

  hgemm_w<1><<<dim3(32, 32), 256, HW_SMEM>>>(h_p, w1_p, b1, ffn_p, FFDIM, DMODEL);

  hgemm_n<<<dim3(16, 32), 256, HN_SMEM>>>(ffn_p, w2_p, b2, x1_p, out,
                                          DMODEL, FFDIM);
}